// round 8
// baseline (speedup 1.0000x reference)
#include <cuda_runtime.h>
#include <cstdint>

#define Hh 56
#define Ww 56
#define HO 58
#define WO 58
#define PLANE_IN  3136   // 56*56
#define PLANE_OUT 3364   // 58*58
// C fixed at 128 by the generator
#define C_LOG2 7
#define C_MASK 127

__global__ void __launch_bounds__(256, 8)
weight_pad2d_kernel(const float* __restrict__ x,
                    const float* __restrict__ topW,
                    const float* __restrict__ botW,
                    const float* __restrict__ leftW,
                    const float* __restrict__ rightW,
                    const float* __restrict__ topleftW,
                    const float* __restrict__ toprightW,
                    const float* __restrict__ botleftW,
                    const float* __restrict__ botrightW,
                    const int* __restrict__ num_patches_ptr,
                    int planes,
                    float* __restrict__ out)
{
    const int tid  = threadIdx.x;
    const int warp = tid >> 5;           // 0..7
    const int lane = tid & 31;

    const int P  = *num_patches_ptr;
    const int PP = P * P;

    const bool act = (lane < 29);              // lanes 0..28 load & store
    const int  col = (2 * lane < 54) ? 2 * lane : 54;   // lane 27,28 -> col 54

    for (int plane = blockIdx.x; plane < planes; plane += gridDim.x) {
        const int bidx = plane >> C_LOG2;
        const int ch   = plane & C_MASK;

        const unsigned q1 = (unsigned)bidx / (unsigned)P;
        const int colp    = bidx - (int)(q1 * (unsigned)P);       // bidx % P
        const unsigned q2 = (unsigned)bidx / (unsigned)PP;
        const int within  = bidx - (int)(q2 * (unsigned)PP);      // bidx % PP

        const bool topz   = within < P;
        const bool botz   = within >= PP - P;
        const bool leftz  = colp == 0;
        const bool rightz = colp == (P - 1);

        const float* __restrict__ xp = x   + (size_t)plane * PLANE_IN;
        float*       __restrict__ op = out + (size_t)plane * PLANE_OUT;

        // ---- peeled top row (r=0): warps 0,1 scalar (default cache: rows re-read) ----
        if (tid < 64) {
            const int c = tid;
            if (c < WO) {
                float v;
                if (c == 0) {
                    v = (topz || leftz) ? 0.0f : topleftW[ch] * xp[0];
                } else if (c == WO - 1) {
                    v = (topz || rightz) ? 0.0f : toprightW[ch] * xp[Ww - 1];
                } else {
                    v = topz ? 0.0f : topW[ch] * (xp[c - 1] + xp[Ww + c - 1]);
                }
                __stcs(op + c, v);
            }
        } else if (tid < 128) {
            // ---- peeled bottom row (r=57): warps 2,3 scalar ----
            const int c = tid - 64;
            if (c < WO) {
                const float* x54 = xp + (Hh - 2) * Ww;
                const float* x55 = xp + (Hh - 1) * Ww;
                float v;
                if (c == 0) {
                    v = (botz || leftz) ? 0.0f : botleftW[ch] * x55[0];
                } else if (c == WO - 1) {
                    v = (botz || rightz) ? 0.0f : botrightW[ch] * x55[Ww - 1];
                } else {
                    v = botz ? 0.0f : botW[ch] * (x54[c - 1] + x55[c - 1]);
                }
                __stcs(op + (HO - 1) * WO + c, v);
            }
        }

        // ---- interior rows r = 1..56: one warp per row, float2, single shuffle ----
        const float wLr = leftz  ? 0.0f : leftW[ch];
        const float wRr = rightz ? 0.0f : rightW[ch];

        // Phase 1: batch all 7 loads (MLP = 7). Boundary row groups (k=0,k=6)
        // use default caching because rows 0,1,54,55 are re-read by edge warps.
        float2 g[7];
        #pragma unroll
        for (int k = 0; k < 7; k++) {
            g[k] = make_float2(0.0f, 0.0f);
            if (act) {
                const float2* p = (const float2*)(xp + (warp + 8 * k) * Ww + col);
                g[k] = (k == 0 || k == 6) ? *p : __ldcs(p);
            }
        }

        // Phase 2: one shuffle + selects + store per row
        #pragma unroll
        for (int k = 0; k < 7; k++) {
            const int r = 1 + warp + 8 * k;
            const float upy = __shfl_up_sync(0xffffffffu, g[k].y, 1);
            if (act) {
                const float edge = g[k].x + g[k].y;
                const float o_lo = (lane == 0)  ? wLr * edge : upy;
                const float o_hi = (lane == 28) ? wRr * edge : g[k].x;
                __stcs((float2*)(op + r * WO + 2 * lane), make_float2(o_lo, o_hi));
            }
        }
    }
}

extern "C" void kernel_launch(void* const* d_in, const int* in_sizes, int n_in,
                              void* d_out, int out_size)
{
    const float* x         = (const float*)d_in[0];
    const float* topW      = (const float*)d_in[1];
    const float* botW      = (const float*)d_in[2];
    const float* leftW     = (const float*)d_in[3];
    const float* rightW    = (const float*)d_in[4];
    const float* topleftW  = (const float*)d_in[5];
    const float* toprightW = (const float*)d_in[6];
    const float* botleftW  = (const float*)d_in[7];
    const float* botrightW = (const float*)d_in[8];
    const int*   num_patches = (const int*)d_in[10];

    const int planes = in_sizes[0] / PLANE_IN;   // b * C = 16384

    int grid = 148 * 8;
    if (grid > planes) grid = planes;

    weight_pad2d_kernel<<<grid, 256>>>(
        x, topW, botW, leftW, rightW,
        topleftW, toprightW, botleftW, botrightW,
        num_patches, planes, (float*)d_out);
}